// round 14
// baseline (speedup 1.0000x reference)
#include <cuda_runtime.h>
#include <cuda_fp16.h>
#include <math.h>
#include <stdint.h>

#define V 32000
#define H 1024
#define T 32
#define B 64
#define SOS_INDEX 1
#define EOS_INDEX 2
#define GATES (4*H)

#define RSCALE 2048.0f
#define RINV   (1.0f / 2048.0f)

// ---------------------------------------------------------------------------
// Persistent state. EVERY global that receives accesses wider than 4 bytes
// is vector-typed and accessed by vector-unit indexing.
// ---------------------------------------------------------------------------
__device__ float4 g_c_raw[B*H/4];
__device__ float4 g_gates_raw[B*GATES/4];
__device__ uint4  g_xH_raw[B*H/8];
__device__ uint4  g_xL_raw[B*H/8];
__device__ uint4  g_hH_raw[B*H/8];
__device__ uint4  g_hL_raw[B*H/8];
__device__ uint4  g_WihH_raw[GATES*H/8];
__device__ uint4  g_WihL_raw[GATES*H/8];
__device__ uint4  g_WhhH_raw[GATES*H/8];
__device__ uint4  g_WhhL_raw[GATES*H/8];
__device__ uint4  g_WoutH_raw[(size_t)V*H/8];
__device__ uint4  g_WoutL_raw[(size_t)V*H/8];

#define g_c     ((float*)g_c_raw)
#define g_gates ((float*)g_gates_raw)
#define g_xH    ((__half*)g_xH_raw)
#define g_xL    ((__half*)g_xL_raw)
#define g_hH    ((__half*)g_hH_raw)
#define g_hL    ((__half*)g_hL_raw)

// ---------------------------------------------------------------------------
__device__ __forceinline__ void split_f16(float x, __half& hi, __half& lo) {
    hi = __float2half_rn(x);
    lo = __float2half_rn((x - __half2float(hi)) * RSCALE);
}
__device__ __forceinline__ uint32_t pack2(__half a, __half b) {
    __half2 h = __halves2half2(a, b);
    return *reinterpret_cast<uint32_t*>(&h);
}
__device__ __forceinline__ void mma_f16(float c[4], const uint32_t a[4],
                                        uint32_t b0, uint32_t b1) {
    asm volatile(
        "mma.sync.aligned.m16n8k16.row.col.f32.f16.f16.f32 "
        "{%0,%1,%2,%3}, {%4,%5,%6,%7}, {%8,%9}, {%0,%1,%2,%3};"
        : "+f"(c[0]), "+f"(c[1]), "+f"(c[2]), "+f"(c[3])
        : "r"(a[0]), "r"(a[1]), "r"(a[2]), "r"(a[3]), "r"(b0), "r"(b1));
}
__device__ __forceinline__ void ldsm4(uint32_t r[4], uint32_t addr) {
    asm volatile(
        "ldmatrix.sync.aligned.m8n8.x4.shared.b16 {%0,%1,%2,%3}, [%4];"
        : "=r"(r[0]), "=r"(r[1]), "=r"(r[2]), "=r"(r[3]) : "r"(addr));
}
__device__ __forceinline__ void cp16(uint32_t dst_smem, const uint4* src) {
    asm volatile("cp.async.cg.shared.global [%0], [%1], 16;"
                 :: "r"(dst_smem), "l"(src));
}

// ---------------------------------------------------------------------------
// Weight pre-split: one float4 -> one uint2 of hi halves + one of lo halves.
// ---------------------------------------------------------------------------
__global__ __launch_bounds__(256)
void split_weights(const float4* __restrict__ W, uint2* __restrict__ WH,
                   uint2* __restrict__ WL) {
    size_t j = (size_t)blockIdx.x * 256 + threadIdx.x;   // float4 index
    float4 v = W[j];
    __half h0, l0, h1, l1, h2, l2, h3, l3;
    split_f16(v.x, h0, l0); split_f16(v.y, h1, l1);
    split_f16(v.z, h2, l2); split_f16(v.w, h3, l3);
    WH[j] = make_uint2(pack2(h0, h1), pack2(h2, h3));
    WL[j] = make_uint2(pack2(l0, l1), pack2(l2, l3));
}

// ---------------------------------------------------------------------------
__global__ void init_kernel(const float* __restrict__ E,
                            const float* __restrict__ eh,
                            const float* __restrict__ ec) {
    int i = blockIdx.x * blockDim.x + threadIdx.x;   // 0 .. B*H
    int k = i & (H - 1);
    __half hi, lo;
    split_f16(E[SOS_INDEX * H + k], hi, lo);
    g_xH[i] = hi; g_xL[i] = lo;
    split_f16(eh[i], hi, lo);
    g_hH[i] = hi; g_hL[i] = lo;
    g_c[i] = ec[i];
}

// ---------------------------------------------------------------------------
// Pure-fp16 tensor-core GEMM on pre-split operands.
//   C = Ah*Bh + (Al*Bh + Ah*Bl) / 2048
// 2-stage cp.async pipeline + ldmatrix.x4 fragment loads (6 LDSM feed 12
// HMMA per k16-step). Stage layout (uint4): AsH[64][9] AsL[64][9]
// BsH[BN][9] BsL[BN][9]; 144-byte rows (conflict-free LDSM phases).
// ---------------------------------------------------------------------------
#define BKH 64      // halves of K per tile
#define ROWU 9      // uint4 per SMEM row (8 data + 1 skew)
#define ROWB (ROWU*16)  // bytes per row = 144

template<int KTOT, int BN, bool CONCAT>
__global__ __launch_bounds__(256)
void mma_gemm(const uint4* __restrict__ BaH, const uint4* __restrict__ BaL,
              const uint4* __restrict__ BbH, const uint4* __restrict__ BbL,
              const float* __restrict__ bias1, const float* __restrict__ bias2,
              float* __restrict__ out, int ldc) {
    constexpr int NF  = BN / 16;              // n8 fragments per warp
    constexpr int NP  = NF / 2;               // ldmatrix B pairs per warp
    constexpr int BR  = BN / 32;              // B loader row chunks
    constexpr int STG = (128 + 2 * BN) * ROWU;// uint4 per stage
    constexpr int NT  = KTOT / BKH;           // number of k tiles
    extern __shared__ uint4 smem[];

    const int n0blk = blockIdx.x * BN;
    const int tid   = threadIdx.x;
    const int warp  = tid >> 5;
    const int lane  = tid & 31;
    const int gid   = lane >> 2;
    const int tig   = lane & 3;

    const int m0  = (warp >> 1) * 16;      // warp M offset (0,16,32,48)
    const int n0w = (warp & 1) * (BN / 2); // warp N offset

    const int lm  = tid >> 3;              // loader row 0..31
    const int lv  = tid & 7;               // loader uint4 column 0..7

    // ---- per-thread ldmatrix byte offsets within a stage ----
    // A (m16k16, x4): row = m0 + (lane&15), col-half = 8*(lane>>4) halves
    const uint32_t aoffH = (uint32_t)(m0 + (lane & 15)) * ROWB + 16u * (lane >> 4);
    const uint32_t aoffL = aoffH + 64u * ROWB;
    // B pair p (two n8k16 frags): row = n0w + 16p + (lane&7) + 8*(lane>>4),
    // col-half = 8*((lane>>3)&1) halves
    uint32_t boffH[NP], boffL[NP];
    #pragma unroll
    for (int p = 0; p < NP; p++) {
        uint32_t br = (uint32_t)(n0w + 16 * p + (lane & 7) + 8 * (lane >> 4));
        boffH[p] = (128u + br) * ROWB + 16u * ((lane >> 3) & 1);
        boffL[p] = boffH[p] + (uint32_t)BN * ROWB;
    }
    const uint32_t smem_base = (uint32_t)__cvta_generic_to_shared(smem);

    auto issue_tile = [&](int k0, int stage) {
        uint4* sb = smem + (size_t)stage * STG;
        const int kv = (k0 >> 3) + lv;     // uint4 column in K
        #pragma unroll
        for (int r = 0; r < 2; r++) {
            int m = lm + r * 32;
            uint32_t dH = (uint32_t)__cvta_generic_to_shared(sb + m * ROWU + lv);
            uint32_t dL = (uint32_t)__cvta_generic_to_shared(sb + (64 + m) * ROWU + lv);
            const uint4 *sH, *sL;
            if (CONCAT) {
                if (kv < H / 8) {
                    sH = g_xH_raw + m * (H / 8) + kv;
                    sL = g_xL_raw + m * (H / 8) + kv;
                } else {
                    sH = g_hH_raw + m * (H / 8) + kv - H / 8;
                    sL = g_hL_raw + m * (H / 8) + kv - H / 8;
                }
            } else {
                sH = g_hH_raw + m * (H / 8) + kv;
                sL = g_hL_raw + m * (H / 8) + kv;
            }
            cp16(dH, sH);
            cp16(dL, sL);
        }
        #pragma unroll
        for (int r = 0; r < BR; r++) {
            int nloc = lm + r * 32;
            size_t n = (size_t)n0blk + nloc;
            uint32_t dH = (uint32_t)__cvta_generic_to_shared(sb + (128 + nloc) * ROWU + lv);
            uint32_t dL = (uint32_t)__cvta_generic_to_shared(sb + (128 + BN + nloc) * ROWU + lv);
            const uint4 *sH, *sL;
            if (CONCAT) {
                if (kv < H / 8) {
                    sH = BaH + n * (H / 8) + kv;
                    sL = BaL + n * (H / 8) + kv;
                } else {
                    sH = BbH + n * (H / 8) + kv - H / 8;
                    sL = BbL + n * (H / 8) + kv - H / 8;
                }
            } else {
                sH = BaH + n * (KTOT / 8) + kv;
                sL = BaL + n * (KTOT / 8) + kv;
            }
            cp16(dH, sH);
            cp16(dL, sL);
        }
        asm volatile("cp.async.commit_group;" ::: "memory");
    };

    float c1[NF][4], c2[NF][4];
    #pragma unroll
    for (int nf = 0; nf < NF; nf++)
        #pragma unroll
        for (int j = 0; j < 4; j++) { c1[nf][j] = 0.f; c2[nf][j] = 0.f; }

    issue_tile(0, 0);

    #pragma unroll 1
    for (int kt = 0; kt < NT; kt++) {
        if (kt + 1 < NT) {
            issue_tile((kt + 1) * BKH, (kt + 1) & 1);
            asm volatile("cp.async.wait_group 1;" ::: "memory");
        } else {
            asm volatile("cp.async.wait_group 0;" ::: "memory");
        }
        __syncthreads();

        const uint32_t stg = smem_base + (uint32_t)(kt & 1) * (STG * 16);

        #pragma unroll
        for (int ks = 0; ks < BKH / 16; ks++) {
            const uint32_t koff = ks * 32;   // 16 halves = 32 bytes
            uint32_t ah[4], al[4];
            ldsm4(ah, stg + aoffH + koff);
            ldsm4(al, stg + aoffL + koff);
            // bhr/blr layout: [2*nf] = b0 of frag nf, [2*nf+1] = b1 of frag nf
            uint32_t bhr[2 * NF], blr[2 * NF];
            #pragma unroll
            for (int p = 0; p < NP; p++) {
                ldsm4(&bhr[4 * p], stg + boffH[p] + koff);
                ldsm4(&blr[4 * p], stg + boffL[p] + koff);
            }
            #pragma unroll
            for (int nf = 0; nf < NF; nf++) mma_f16(c2[nf], al, bhr[2*nf], bhr[2*nf+1]);
            #pragma unroll
            for (int nf = 0; nf < NF; nf++) mma_f16(c1[nf], ah, bhr[2*nf], bhr[2*nf+1]);
            #pragma unroll
            for (int nf = 0; nf < NF; nf++) mma_f16(c2[nf], ah, blr[2*nf], blr[2*nf+1]);
        }
        __syncthreads();
    }

    // ---- epilogue: combine chains + bias + SCALAR float stores ----
    const int mr0 = m0 + gid;
    const int mr1 = m0 + gid + 8;
    #pragma unroll
    for (int nf = 0; nf < NF; nf++) {
        int nn = n0blk + n0w + nf * 8 + tig * 2;
        float b0 = bias1[nn]     + (CONCAT ? bias2[nn]     : 0.f);
        float b1 = bias1[nn + 1] + (CONCAT ? bias2[nn + 1] : 0.f);
        out[(size_t)mr0 * ldc + nn]     = c1[nf][0] + c2[nf][0] * RINV + b0;
        out[(size_t)mr0 * ldc + nn + 1] = c1[nf][1] + c2[nf][1] * RINV + b1;
        out[(size_t)mr1 * ldc + nn]     = c1[nf][2] + c2[nf][2] * RINV + b0;
        out[(size_t)mr1 * ldc + nn + 1] = c1[nf][3] + c2[nf][3] * RINV + b1;
    }
}

// ---------------------------------------------------------------------------
// LSTM cell: writes c (f32) and SPLIT h (scalar halves).
// ---------------------------------------------------------------------------
__global__ void cell_kernel() {
    int i = blockIdx.x * blockDim.x + threadIdx.x;   // B*H
    int b = i >> 10;
    int j = i & (H - 1);
    const float* g = g_gates + b * GATES;
    float ig = g[j], fg = g[j + H], gg = g[j + 2 * H], og = g[j + 3 * H];
    float c  = g_c[i];
    float si = 1.f / (1.f + expf(-ig));
    float sf = 1.f / (1.f + expf(-fg));
    float so = 1.f / (1.f + expf(-og));
    float cn = sf * c + si * tanhf(gg);
    float hn = so * tanhf(cn);
    g_c[i] = cn;
    __half hi, lo;
    split_f16(hn, hi, lo);
    g_hH[i] = hi; g_hL[i] = lo;
}

// ---------------------------------------------------------------------------
// Per-batch-row: argmax (first-index tiebreak), softmax EOS prob,
// greedy feedback gather x_next = E[argmax] written pre-split (scalar).
// ---------------------------------------------------------------------------
__global__ __launch_bounds__(1024)
void softmax_argmax(const float* __restrict__ logits, const float* __restrict__ E,
                    float* __restrict__ mask_out) {
    const int b    = blockIdx.x;
    const int tid  = threadIdx.x;
    const int lane = tid & 31;
    const int wrp  = tid >> 5;
    const float4* row4 = reinterpret_cast<const float4*>(logits + (size_t)b * V);

    float best = -INFINITY; int besti = 0x7fffffff;
    for (int q = tid; q < V / 4; q += 1024) {
        float4 x = row4[q];
        int v = q * 4;
        if (x.x > best) { best = x.x; besti = v; }
        if (x.y > best) { best = x.y; besti = v + 1; }
        if (x.z > best) { best = x.z; besti = v + 2; }
        if (x.w > best) { best = x.w; besti = v + 3; }
    }
    #pragma unroll
    for (int s = 16; s > 0; s >>= 1) {
        float ov = __shfl_down_sync(0xffffffffu, best, s);
        int   oi = __shfl_down_sync(0xffffffffu, besti, s);
        if (ov > best || (ov == best && oi < besti)) { best = ov; besti = oi; }
    }
    __shared__ float swv[32];
    __shared__ int   swi[32];
    if (lane == 0) { swv[wrp] = best; swi[wrp] = besti; }
    __syncthreads();
    __shared__ float s_gmax;
    __shared__ int   s_amax;
    if (wrp == 0) {
        float bv = swv[lane]; int bi = swi[lane];
        #pragma unroll
        for (int s = 16; s > 0; s >>= 1) {
            float ov = __shfl_down_sync(0xffffffffu, bv, s);
            int   oi = __shfl_down_sync(0xffffffffu, bi, s);
            if (ov > bv || (ov == bv && oi < bi)) { bv = ov; bi = oi; }
        }
        if (lane == 0) { s_gmax = bv; s_amax = bi; }
    }
    __syncthreads();
    const float gmax = s_gmax;
    const int   amax = s_amax;

    float sum = 0.f;
    for (int q = tid; q < V / 4; q += 1024) {
        float4 x = row4[q];
        sum += expf(x.x - gmax) + expf(x.y - gmax)
             + expf(x.z - gmax) + expf(x.w - gmax);
    }
    #pragma unroll
    for (int s = 16; s > 0; s >>= 1)
        sum += __shfl_down_sync(0xffffffffu, sum, s);
    __shared__ float ssum[32];
    if (lane == 0) ssum[wrp] = sum;
    __syncthreads();
    if (wrp == 0) {
        float t = ssum[lane];
        #pragma unroll
        for (int s = 16; s > 0; s >>= 1)
            t += __shfl_down_sync(0xffffffffu, t, s);
        if (lane == 0)
            mask_out[b] = expf(logits[(size_t)b * V + EOS_INDEX] - gmax) / t;
    }

    // greedy feedback: x_next = E[argmax], stored pre-split (scalar 2B)
    __half hi, lo;
    split_f16(E[(size_t)amax * H + tid], hi, lo);
    g_xH[b * H + tid] = hi;
    g_xL[b * H + tid] = lo;
}

// ---------------------------------------------------------------------------
extern "C" void kernel_launch(void* const* d_in, const int* in_sizes, int n_in,
                              void* d_out, int out_size) {
    const float* E    = (const float*)d_in[0];
    const float* Wih  = (const float*)d_in[1];
    const float* Whh  = (const float*)d_in[2];
    const float* bih  = (const float*)d_in[3];
    const float* bhh  = (const float*)d_in[4];
    const float* Wout = (const float*)d_in[5];
    const float* bout = (const float*)d_in[6];
    const float* eh   = (const float*)d_in[7];
    const float* ec   = (const float*)d_in[8];

    float* out   = (float*)d_out;                       // [T][B][V] logits
    float* masks = out + (size_t)T * B * V;             // [T][B]

    // Resolve DEVICE addresses of all symbols passed as kernel args.
    void *pWihH, *pWihL, *pWhhH, *pWhhL, *pWoutH, *pWoutL, *pGates;
    cudaGetSymbolAddress(&pWihH, g_WihH_raw);
    cudaGetSymbolAddress(&pWihL, g_WihL_raw);
    cudaGetSymbolAddress(&pWhhH, g_WhhH_raw);
    cudaGetSymbolAddress(&pWhhL, g_WhhL_raw);
    cudaGetSymbolAddress(&pWoutH, g_WoutH_raw);
    cudaGetSymbolAddress(&pWoutL, g_WoutL_raw);
    cudaGetSymbolAddress(&pGates, g_gates_raw);

    // Dynamic SMEM sizes (2 stages).
    const int smem_gates  = (128 + 2 * 32) * ROWU * 16 * 2;   // 55296 B
    const int smem_logits = (128 + 2 * 64) * ROWU * 16 * 2;   // 73728 B
    cudaFuncSetAttribute(mma_gemm<2 * H, 32, true>,
                         cudaFuncAttributeMaxDynamicSharedMemorySize, smem_gates);
    cudaFuncSetAttribute(mma_gemm<H, 64, false>,
                         cudaFuncAttributeMaxDynamicSharedMemorySize, smem_logits);

    // One-time (per launch) weight pre-split. grid = elems/4/256.
    split_weights<<<GATES * H / 1024, 256>>>(
        (const float4*)Wih, (uint2*)pWihH, (uint2*)pWihL);
    split_weights<<<GATES * H / 1024, 256>>>(
        (const float4*)Whh, (uint2*)pWhhH, (uint2*)pWhhL);
    split_weights<<<(int)((size_t)V * H / 1024), 256>>>(
        (const float4*)Wout, (uint2*)pWoutH, (uint2*)pWoutL);

    init_kernel<<<(B * H) / 256, 256>>>(E, eh, ec);
    for (int t = 0; t < T; t++) {
        float* lg = out + (size_t)t * B * V;
        // gates: [64 x 4096] = [x|h] * [Wih|Whh]^T, BN=32 -> 128 blocks
        mma_gemm<2 * H, 32, true><<<GATES / 32, 256, smem_gates>>>(
            (const uint4*)pWihH, (const uint4*)pWihL,
            (const uint4*)pWhhH, (const uint4*)pWhhL,
            bih, bhh, (float*)pGates, GATES);
        cell_kernel<<<(B * H) / 256, 256>>>();
        // logits: [64 x 32000] = h * Wout^T, BN=64 -> 500 blocks
        mma_gemm<H, 64, false><<<V / 64, 256, smem_logits>>>(
            (const uint4*)pWoutH, (const uint4*)pWoutL,
            nullptr, nullptr, bout, nullptr, lg, V);
        softmax_argmax<<<B, 1024>>>(lg, E, masks + t * B);
    }
}

// round 15
// speedup vs baseline: 1.4066x; 1.4066x over previous
#include <cuda_runtime.h>
#include <cuda_fp16.h>
#include <math.h>
#include <stdint.h>

#define V 32000
#define H 1024
#define T 32
#define B 64
#define SOS_INDEX 1
#define EOS_INDEX 2
#define GATES (4*H)

#define RSCALE 2048.0f
#define RINV   (1.0f / 2048.0f)

// ---------------------------------------------------------------------------
// Persistent state. EVERY global that receives accesses wider than 4 bytes
// is vector-typed and accessed by vector-unit indexing.
// ---------------------------------------------------------------------------
__device__ float4 g_c_raw[B*H/4];
__device__ uint4  g_xH_raw[B*H/8];
__device__ uint4  g_xL_raw[B*H/8];
__device__ uint4  g_hH_raw[B*H/8];
__device__ uint4  g_hL_raw[B*H/8];
__device__ uint4  g_WihH_raw[GATES*H/8];
__device__ uint4  g_WihL_raw[GATES*H/8];
__device__ uint4  g_WhhH_raw[GATES*H/8];
__device__ uint4  g_WhhL_raw[GATES*H/8];
__device__ uint4  g_WoutH_raw[(size_t)V*H/8];
__device__ uint4  g_WoutL_raw[(size_t)V*H/8];

#define g_c     ((float*)g_c_raw)
#define g_xH    ((__half*)g_xH_raw)
#define g_xL    ((__half*)g_xL_raw)
#define g_hH    ((__half*)g_hH_raw)
#define g_hL    ((__half*)g_hL_raw)

// ---------------------------------------------------------------------------
__device__ __forceinline__ void split_f16(float x, __half& hi, __half& lo) {
    hi = __float2half_rn(x);
    lo = __float2half_rn((x - __half2float(hi)) * RSCALE);
}
__device__ __forceinline__ uint32_t pack2(__half a, __half b) {
    __half2 h = __halves2half2(a, b);
    return *reinterpret_cast<uint32_t*>(&h);
}
__device__ __forceinline__ void mma_f16(float c[4], const uint32_t a[4],
                                        uint32_t b0, uint32_t b1) {
    asm volatile(
        "mma.sync.aligned.m16n8k16.row.col.f32.f16.f16.f32 "
        "{%0,%1,%2,%3}, {%4,%5,%6,%7}, {%8,%9}, {%0,%1,%2,%3};"
        : "+f"(c[0]), "+f"(c[1]), "+f"(c[2]), "+f"(c[3])
        : "r"(a[0]), "r"(a[1]), "r"(a[2]), "r"(a[3]), "r"(b0), "r"(b1));
}
__device__ __forceinline__ void cp16(uint32_t dst_smem, const uint4* src) {
    asm volatile("cp.async.cg.shared.global [%0], [%1], 16;"
                 :: "r"(dst_smem), "l"(src));
}

// ---------------------------------------------------------------------------
// Weight pre-split: one float4 -> one uint2 of hi halves + one of lo halves.
// ---------------------------------------------------------------------------
__global__ __launch_bounds__(256)
void split_weights(const float4* __restrict__ W, uint2* __restrict__ WH,
                   uint2* __restrict__ WL) {
    size_t j = (size_t)blockIdx.x * 256 + threadIdx.x;   // float4 index
    float4 v = W[j];
    __half h0, l0, h1, l1, h2, l2, h3, l3;
    split_f16(v.x, h0, l0); split_f16(v.y, h1, l1);
    split_f16(v.z, h2, l2); split_f16(v.w, h3, l3);
    WH[j] = make_uint2(pack2(h0, h1), pack2(h2, h3));
    WL[j] = make_uint2(pack2(l0, l1), pack2(l2, l3));
}

// ---------------------------------------------------------------------------
__global__ void init_kernel(const float* __restrict__ E,
                            const float* __restrict__ eh,
                            const float* __restrict__ ec) {
    int i = blockIdx.x * blockDim.x + threadIdx.x;   // 0 .. B*H
    int k = i & (H - 1);
    __half hi, lo;
    split_f16(E[SOS_INDEX * H + k], hi, lo);
    g_xH[i] = hi; g_xL[i] = lo;
    split_f16(eh[i], hi, lo);
    g_hH[i] = hi; g_hL[i] = lo;
    g_c[i] = ec[i];
}

#define BKH 64      // halves of K per tile
#define ROWU 9      // uint4 per SMEM row (8 data + 1 skew)
#define ROWH (ROWU*8)

// ---------------------------------------------------------------------------
// Logits GEMM (R13 golden version, unchanged): C[64 x V] = h * Wout^T + bias.
// 2-stage cp.async pipeline, scalar-LDS consumer.
// ---------------------------------------------------------------------------
template<int KTOT, int BN>
__global__ __launch_bounds__(256)
void logits_gemm(const uint4* __restrict__ BaH, const uint4* __restrict__ BaL,
                 const float* __restrict__ bias1, float* __restrict__ out, int ldc) {
    constexpr int NF  = BN / 16;
    constexpr int BR  = BN / 32;
    constexpr int STG = (128 + 2 * BN) * ROWU;
    constexpr int NT  = KTOT / BKH;
    extern __shared__ uint4 smem[];

    const int n0blk = blockIdx.x * BN;
    const int tid   = threadIdx.x;
    const int warp  = tid >> 5;
    const int lane  = tid & 31;
    const int gid   = lane >> 2;
    const int tig   = lane & 3;

    const int m0  = (warp >> 1) * 16;
    const int n0w = (warp & 1) * (BN / 2);

    const int lm  = tid >> 3;
    const int lv  = tid & 7;

    auto issue_tile = [&](int k0, int stage) {
        uint4* sb = smem + (size_t)stage * STG;
        const int kv = (k0 >> 3) + lv;
        #pragma unroll
        for (int r = 0; r < 2; r++) {
            int m = lm + r * 32;
            uint32_t dH = (uint32_t)__cvta_generic_to_shared(sb + m * ROWU + lv);
            uint32_t dL = (uint32_t)__cvta_generic_to_shared(sb + (64 + m) * ROWU + lv);
            cp16(dH, g_hH_raw + m * (H / 8) + kv);
            cp16(dL, g_hL_raw + m * (H / 8) + kv);
        }
        #pragma unroll
        for (int r = 0; r < BR; r++) {
            int nloc = lm + r * 32;
            size_t n = (size_t)n0blk + nloc;
            uint32_t dH = (uint32_t)__cvta_generic_to_shared(sb + (128 + nloc) * ROWU + lv);
            uint32_t dL = (uint32_t)__cvta_generic_to_shared(sb + (128 + BN + nloc) * ROWU + lv);
            cp16(dH, BaH + n * (KTOT / 8) + kv);
            cp16(dL, BaL + n * (KTOT / 8) + kv);
        }
        asm volatile("cp.async.commit_group;" ::: "memory");
    };

    float c1[NF][4], c2[NF][4];
    #pragma unroll
    for (int nf = 0; nf < NF; nf++)
        #pragma unroll
        for (int j = 0; j < 4; j++) { c1[nf][j] = 0.f; c2[nf][j] = 0.f; }

    issue_tile(0, 0);

    #pragma unroll 1
    for (int kt = 0; kt < NT; kt++) {
        if (kt + 1 < NT) {
            issue_tile((kt + 1) * BKH, (kt + 1) & 1);
            asm volatile("cp.async.wait_group 1;" ::: "memory");
        } else {
            asm volatile("cp.async.wait_group 0;" ::: "memory");
        }
        __syncthreads();

        const __half* base = (const __half*)(smem + (size_t)(kt & 1) * STG);
        const __half* AsH = base;
        const __half* AsL = base + 64 * ROWH;
        const __half* BsH = base + 128 * ROWH;
        const __half* BsL = base + (128 + BN) * ROWH;

        #pragma unroll
        for (int ks = 0; ks < BKH / 16; ks++) {
            const int kb = ks * 16;
            const int ra = (m0 + gid) * ROWH, rb = (m0 + gid + 8) * ROWH;
            uint32_t ah[4], al[4];
            ah[0] = *reinterpret_cast<const uint32_t*>(AsH + ra + kb + 2 * tig);
            ah[1] = *reinterpret_cast<const uint32_t*>(AsH + rb + kb + 2 * tig);
            ah[2] = *reinterpret_cast<const uint32_t*>(AsH + ra + kb + 8 + 2 * tig);
            ah[3] = *reinterpret_cast<const uint32_t*>(AsH + rb + kb + 8 + 2 * tig);
            al[0] = *reinterpret_cast<const uint32_t*>(AsL + ra + kb + 2 * tig);
            al[1] = *reinterpret_cast<const uint32_t*>(AsL + rb + kb + 2 * tig);
            al[2] = *reinterpret_cast<const uint32_t*>(AsL + ra + kb + 8 + 2 * tig);
            al[3] = *reinterpret_cast<const uint32_t*>(AsL + rb + kb + 8 + 2 * tig);

            uint32_t bh[NF][2];
            #pragma unroll
            for (int nf = 0; nf < NF; nf++) {
                int n = (n0w + nf * 8 + gid) * ROWH;
                bh[nf][0] = *reinterpret_cast<const uint32_t*>(BsH + n + kb + 2 * tig);
                bh[nf][1] = *reinterpret_cast<const uint32_t*>(BsH + n + kb + 8 + 2 * tig);
            }
            #pragma unroll
            for (int nf = 0; nf < NF; nf++) mma_f16(c2[nf], al, bh[nf][0], bh[nf][1]);
            #pragma unroll
            for (int nf = 0; nf < NF; nf++) mma_f16(c1[nf], ah, bh[nf][0], bh[nf][1]);
            #pragma unroll
            for (int nf = 0; nf < NF; nf++) {
                int n = (n0w + nf * 8 + gid) * ROWH;
                uint32_t bl0 = *reinterpret_cast<const uint32_t*>(BsL + n + kb + 2 * tig);
                uint32_t bl1 = *reinterpret_cast<const uint32_t*>(BsL + n + kb + 8 + 2 * tig);
                mma_f16(c2[nf], ah, bl0, bl1);
            }
        }
        __syncthreads();
    }

    const int mr0 = m0 + gid;
    const int mr1 = m0 + gid + 8;
    #pragma unroll
    for (int nf = 0; nf < NF; nf++) {
        int nn = n0blk + n0w + nf * 8 + tig * 2;
        float b0 = bias1[nn];
        float b1 = bias1[nn + 1];
        out[(size_t)mr0 * ldc + nn]     = c1[nf][0] + c2[nf][0] * RINV + b0;
        out[(size_t)mr0 * ldc + nn + 1] = c1[nf][1] + c2[nf][1] * RINV + b1;
        out[(size_t)mr1 * ldc + nn]     = c1[nf][2] + c2[nf][2] * RINV + b0;
        out[(size_t)mr1 * ldc + nn + 1] = c1[nf][3] + c2[nf][3] * RINV + b1;
    }
}

// ---------------------------------------------------------------------------
// FUSED gates GEMM + LSTM cell. Block x computes weight rows
// {gate*H + 8x + r : gate=0..3, r=0..7} (local n = gate*8 + r, BN=32),
// spills the 64x32 gate tile to SMEM, then applies the cell update in-kernel:
// reads g_c, writes g_c and the SPLIT h. Eliminates cell_kernel + g_gates.
// ---------------------------------------------------------------------------
__global__ __launch_bounds__(256)
void gates_cell_gemm(const uint4* __restrict__ WihH, const uint4* __restrict__ WihL,
                     const uint4* __restrict__ WhhH, const uint4* __restrict__ WhhL,
                     const float* __restrict__ bih, const float* __restrict__ bhh) {
    constexpr int BN  = 32;
    constexpr int NF  = 2;
    constexpr int STG = (128 + 2 * BN) * ROWU;
    constexpr int KTOT = 2 * H;
    constexpr int NT  = KTOT / BKH;
    extern __shared__ uint4 smem[];

    const int J0  = blockIdx.x * 8;        // j-range of this block
    const int tid = threadIdx.x;
    const int warp = tid >> 5;
    const int lane = tid & 31;
    const int gid  = lane >> 2;
    const int tig  = lane & 3;

    const int m0  = (warp >> 1) * 16;
    const int n0w = (warp & 1) * (BN / 2);

    const int lm  = tid >> 3;
    const int lv  = tid & 7;

    // local n -> global weight row
    auto grow_of = [&](int nloc) { return (nloc >> 3) * H + J0 + (nloc & 7); };

    auto issue_tile = [&](int k0, int stage) {
        uint4* sb = smem + (size_t)stage * STG;
        const int kv = (k0 >> 3) + lv;
        #pragma unroll
        for (int r = 0; r < 2; r++) {
            int m = lm + r * 32;
            uint32_t dH = (uint32_t)__cvta_generic_to_shared(sb + m * ROWU + lv);
            uint32_t dL = (uint32_t)__cvta_generic_to_shared(sb + (64 + m) * ROWU + lv);
            if (kv < H / 8) {
                cp16(dH, g_xH_raw + m * (H / 8) + kv);
                cp16(dL, g_xL_raw + m * (H / 8) + kv);
            } else {
                cp16(dH, g_hH_raw + m * (H / 8) + kv - H / 8);
                cp16(dL, g_hL_raw + m * (H / 8) + kv - H / 8);
            }
        }
        {
            int nloc = lm;                  // BR = 1 for BN=32
            size_t n = (size_t)grow_of(nloc);
            uint32_t dH = (uint32_t)__cvta_generic_to_shared(sb + (128 + nloc) * ROWU + lv);
            uint32_t dL = (uint32_t)__cvta_generic_to_shared(sb + (128 + BN + nloc) * ROWU + lv);
            if (kv < H / 8) {
                cp16(dH, WihH + n * (H / 8) + kv);
                cp16(dL, WihL + n * (H / 8) + kv);
            } else {
                cp16(dH, WhhH + n * (H / 8) + kv - H / 8);
                cp16(dL, WhhL + n * (H / 8) + kv - H / 8);
            }
        }
        asm volatile("cp.async.commit_group;" ::: "memory");
    };

    float c1[NF][4], c2[NF][4];
    #pragma unroll
    for (int nf = 0; nf < NF; nf++)
        #pragma unroll
        for (int j = 0; j < 4; j++) { c1[nf][j] = 0.f; c2[nf][j] = 0.f; }

    issue_tile(0, 0);

    #pragma unroll 1
    for (int kt = 0; kt < NT; kt++) {
        if (kt + 1 < NT) {
            issue_tile((kt + 1) * BKH, (kt + 1) & 1);
            asm volatile("cp.async.wait_group 1;" ::: "memory");
        } else {
            asm volatile("cp.async.wait_group 0;" ::: "memory");
        }
        __syncthreads();

        const __half* base = (const __half*)(smem + (size_t)(kt & 1) * STG);
        const __half* AsH = base;
        const __half* AsL = base + 64 * ROWH;
        const __half* BsH = base + 128 * ROWH;
        const __half* BsL = base + (128 + BN) * ROWH;

        #pragma unroll
        for (int ks = 0; ks < BKH / 16; ks++) {
            const int kb = ks * 16;
            const int ra = (m0 + gid) * ROWH, rb = (m0 + gid + 8) * ROWH;
            uint32_t ah[4], al[4];
            ah[0] = *reinterpret_cast<const uint32_t*>(AsH + ra + kb + 2 * tig);
            ah[1] = *reinterpret_cast<const uint32_t*>(AsH + rb + kb + 2 * tig);
            ah[2] = *reinterpret_cast<const uint32_t*>(AsH + ra + kb + 8 + 2 * tig);
            ah[3] = *reinterpret_cast<const uint32_t*>(AsH + rb + kb + 8 + 2 * tig);
            al[0] = *reinterpret_cast<const uint32_t*>(AsL + ra + kb + 2 * tig);
            al[1] = *reinterpret_cast<const uint32_t*>(AsL + rb + kb + 2 * tig);
            al[2] = *reinterpret_cast<const uint32_t*>(AsL + ra + kb + 8 + 2 * tig);
            al[3] = *reinterpret_cast<const uint32_t*>(AsL + rb + kb + 8 + 2 * tig);

            uint32_t bh[NF][2];
            #pragma unroll
            for (int nf = 0; nf < NF; nf++) {
                int n = (n0w + nf * 8 + gid) * ROWH;
                bh[nf][0] = *reinterpret_cast<const uint32_t*>(BsH + n + kb + 2 * tig);
                bh[nf][1] = *reinterpret_cast<const uint32_t*>(BsH + n + kb + 8 + 2 * tig);
            }
            #pragma unroll
            for (int nf = 0; nf < NF; nf++) mma_f16(c2[nf], al, bh[nf][0], bh[nf][1]);
            #pragma unroll
            for (int nf = 0; nf < NF; nf++) mma_f16(c1[nf], ah, bh[nf][0], bh[nf][1]);
            #pragma unroll
            for (int nf = 0; nf < NF; nf++) {
                int n = (n0w + nf * 8 + gid) * ROWH;
                uint32_t bl0 = *reinterpret_cast<const uint32_t*>(BsL + n + kb + 2 * tig);
                uint32_t bl1 = *reinterpret_cast<const uint32_t*>(BsL + n + kb + 8 + 2 * tig);
                mma_f16(c2[nf], ah, bl0, bl1);
            }
        }
        __syncthreads();
    }

    // ---- epilogue: spill gate tile (64 x 32) to SMEM, then fused cell ----
    float* sg = (float*)smem;              // 64*32*4 = 8 KB (pipeline smem dead)
    const int mr0 = m0 + gid;
    const int mr1 = m0 + gid + 8;
    #pragma unroll
    for (int nf = 0; nf < NF; nf++) {
        int nloc = n0w + nf * 8 + tig * 2;
        int gr0 = grow_of(nloc), gr1 = grow_of(nloc + 1);
        float b0 = bih[gr0] + bhh[gr0];
        float b1 = bih[gr1] + bhh[gr1];
        sg[mr0 * 32 + nloc]     = c1[nf][0] + c2[nf][0] * RINV + b0;
        sg[mr0 * 32 + nloc + 1] = c1[nf][1] + c2[nf][1] * RINV + b1;
        sg[mr1 * 32 + nloc]     = c1[nf][2] + c2[nf][2] * RINV + b0;
        sg[mr1 * 32 + nloc + 1] = c1[nf][3] + c2[nf][3] * RINV + b1;
    }
    __syncthreads();

    // 512 (b, r) elements, 256 threads -> 2 each
    #pragma unroll
    for (int e = tid; e < 512; e += 256) {
        int b = e >> 3, r = e & 7;
        float ig = sg[b * 32 + r];
        float fg = sg[b * 32 + 8 + r];
        float gg = sg[b * 32 + 16 + r];
        float og = sg[b * 32 + 24 + r];
        int idx = b * H + J0 + r;
        float c  = g_c[idx];
        float si = 1.f / (1.f + expf(-ig));
        float sf = 1.f / (1.f + expf(-fg));
        float so = 1.f / (1.f + expf(-og));
        float cn = sf * c + si * tanhf(gg);
        float hn = so * tanhf(cn);
        g_c[idx] = cn;
        __half hi, lo;
        split_f16(hn, hi, lo);
        g_hH[idx] = hi; g_hL[idx] = lo;
    }
}

// ---------------------------------------------------------------------------
// Per-batch-row: argmax (first-index tiebreak), softmax EOS prob,
// greedy feedback gather x_next = E[argmax] written pre-split (scalar).
// ---------------------------------------------------------------------------
__global__ __launch_bounds__(1024)
void softmax_argmax(const float* __restrict__ logits, const float* __restrict__ E,
                    float* __restrict__ mask_out) {
    const int b    = blockIdx.x;
    const int tid  = threadIdx.x;
    const int lane = tid & 31;
    const int wrp  = tid >> 5;
    const float4* row4 = reinterpret_cast<const float4*>(logits + (size_t)b * V);

    float best = -INFINITY; int besti = 0x7fffffff;
    for (int q = tid; q < V / 4; q += 1024) {
        float4 x = row4[q];
        int v = q * 4;
        if (x.x > best) { best = x.x; besti = v; }
        if (x.y > best) { best = x.y; besti = v + 1; }
        if (x.z > best) { best = x.z; besti = v + 2; }
        if (x.w > best) { best = x.w; besti = v + 3; }
    }
    #pragma unroll
    for (int s = 16; s > 0; s >>= 1) {
        float ov = __shfl_down_sync(0xffffffffu, best, s);
        int   oi = __shfl_down_sync(0xffffffffu, besti, s);
        if (ov > best || (ov == best && oi < besti)) { best = ov; besti = oi; }
    }
    __shared__ float swv[32];
    __shared__ int   swi[32];
    if (lane == 0) { swv[wrp] = best; swi[wrp] = besti; }
    __syncthreads();
    __shared__ float s_gmax;
    __shared__ int   s_amax;
    if (wrp == 0) {
        float bv = swv[lane]; int bi = swi[lane];
        #pragma unroll
        for (int s = 16; s > 0; s >>= 1) {
            float ov = __shfl_down_sync(0xffffffffu, bv, s);
            int   oi = __shfl_down_sync(0xffffffffu, bi, s);
            if (ov > bv || (ov == bv && oi < bi)) { bv = ov; bi = oi; }
        }
        if (lane == 0) { s_gmax = bv; s_amax = bi; }
    }
    __syncthreads();
    const float gmax = s_gmax;
    const int   amax = s_amax;

    float sum = 0.f;
    for (int q = tid; q < V / 4; q += 1024) {
        float4 x = row4[q];
        sum += expf(x.x - gmax) + expf(x.y - gmax)
             + expf(x.z - gmax) + expf(x.w - gmax);
    }
    #pragma unroll
    for (int s = 16; s > 0; s >>= 1)
        sum += __shfl_down_sync(0xffffffffu, sum, s);
    __shared__ float ssum[32];
    if (lane == 0) ssum[wrp] = sum;
    __syncthreads();
    if (wrp == 0) {
        float t = ssum[lane];
        #pragma unroll
        for (int s = 16; s > 0; s >>= 1)
            t += __shfl_down_sync(0xffffffffu, t, s);
        if (lane == 0)
            mask_out[b] = expf(logits[(size_t)b * V + EOS_INDEX] - gmax) / t;
    }

    // greedy feedback: x_next = E[argmax], stored pre-split (scalar 2B)
    __half hi, lo;
    split_f16(E[(size_t)amax * H + tid], hi, lo);
    g_xH[b * H + tid] = hi;
    g_xL[b * H + tid] = lo;
}

// ---------------------------------------------------------------------------
extern "C" void kernel_launch(void* const* d_in, const int* in_sizes, int n_in,
                              void* d_out, int out_size) {
    const float* E    = (const float*)d_in[0];
    const float* Wih  = (const float*)d_in[1];
    const float* Whh  = (const float*)d_in[2];
    const float* bih  = (const float*)d_in[3];
    const float* bhh  = (const float*)d_in[4];
    const float* Wout = (const float*)d_in[5];
    const float* bout = (const float*)d_in[6];
    const float* eh   = (const float*)d_in[7];
    const float* ec   = (const float*)d_in[8];

    float* out   = (float*)d_out;                       // [T][B][V] logits
    float* masks = out + (size_t)T * B * V;             // [T][B]

    // Resolve DEVICE addresses of all symbols passed as kernel args.
    void *pWihH, *pWihL, *pWhhH, *pWhhL, *pWoutH, *pWoutL;
    cudaGetSymbolAddress(&pWihH, g_WihH_raw);
    cudaGetSymbolAddress(&pWihL, g_WihL_raw);
    cudaGetSymbolAddress(&pWhhH, g_WhhH_raw);
    cudaGetSymbolAddress(&pWhhL, g_WhhL_raw);
    cudaGetSymbolAddress(&pWoutH, g_WoutH_raw);
    cudaGetSymbolAddress(&pWoutL, g_WoutL_raw);

    // Dynamic SMEM sizes (2 stages).
    const int smem_gates  = (128 + 2 * 32) * ROWU * 16 * 2;   // 55296 B
    const int smem_logits = (128 + 2 * 64) * ROWU * 16 * 2;   // 73728 B
    cudaFuncSetAttribute(gates_cell_gemm,
                         cudaFuncAttributeMaxDynamicSharedMemorySize, smem_gates);
    cudaFuncSetAttribute(logits_gemm<H, 64>,
                         cudaFuncAttributeMaxDynamicSharedMemorySize, smem_logits);

    // One-time (per launch) weight pre-split. grid = elems/4/256.
    split_weights<<<GATES * H / 1024, 256>>>(
        (const float4*)Wih, (uint2*)pWihH, (uint2*)pWihL);
    split_weights<<<GATES * H / 1024, 256>>>(
        (const float4*)Whh, (uint2*)pWhhH, (uint2*)pWhhL);
    split_weights<<<(int)((size_t)V * H / 1024), 256>>>(
        (const float4*)Wout, (uint2*)pWoutH, (uint2*)pWoutL);

    init_kernel<<<(B * H) / 256, 256>>>(E, eh, ec);
    for (int t = 0; t < T; t++) {
        float* lg = out + (size_t)t * B * V;
        // fused gates GEMM + cell: 128 blocks (8 j-values each)
        gates_cell_gemm<<<H / 8, 256, smem_gates>>>(
            (const uint4*)pWihH, (const uint4*)pWihL,
            (const uint4*)pWhhH, (const uint4*)pWhhL, bih, bhh);
        // logits: [64 x 32000] = h * Wout^T, BN=64 -> 500 blocks
        logits_gemm<H, 64><<<V / 64, 256, smem_logits>>>(
            (const uint4*)pWoutH, (const uint4*)pWoutL, bout, lg, V);
        softmax_argmax<<<B, 1024>>>(lg, E, masks + t * B);
    }
}

// round 16
// speedup vs baseline: 1.4943x; 1.0623x over previous
#include <cuda_runtime.h>
#include <cuda_fp16.h>
#include <math.h>
#include <stdint.h>

#define V 32000
#define H 1024
#define T 32
#define B 64
#define SOS_INDEX 1
#define EOS_INDEX 2
#define GATES (4*H)

#define RSCALE 2048.0f
#define RINV   (1.0f / 2048.0f)

// ---------------------------------------------------------------------------
// Persistent state. EVERY global that receives accesses wider than 4 bytes
// is vector-typed and accessed by vector-unit indexing.
// ---------------------------------------------------------------------------
__device__ float4 g_c_raw[B*H/4];
__device__ uint4  g_xH_raw[B*H/8];
__device__ uint4  g_xL_raw[B*H/8];
__device__ uint4  g_hH_raw[B*H/8];
__device__ uint4  g_hL_raw[B*H/8];
__device__ uint4  g_WihH_raw[GATES*H/8];
__device__ uint4  g_WihL_raw[GATES*H/8];
__device__ uint4  g_WhhH_raw[GATES*H/8];
__device__ uint4  g_WhhL_raw[GATES*H/8];
__device__ uint4  g_WoutH_raw[(size_t)V*H/8];
__device__ uint4  g_WoutL_raw[(size_t)V*H/8];

#define g_c     ((float*)g_c_raw)
#define g_xH    ((__half*)g_xH_raw)
#define g_xL    ((__half*)g_xL_raw)
#define g_hH    ((__half*)g_hH_raw)
#define g_hL    ((__half*)g_hL_raw)

// ---------------------------------------------------------------------------
__device__ __forceinline__ void split_f16(float x, __half& hi, __half& lo) {
    hi = __float2half_rn(x);
    lo = __float2half_rn((x - __half2float(hi)) * RSCALE);
}
__device__ __forceinline__ uint32_t pack2(__half a, __half b) {
    __half2 h = __halves2half2(a, b);
    return *reinterpret_cast<uint32_t*>(&h);
}
__device__ __forceinline__ void mma_f16(float c[4], const uint32_t a[4],
                                        uint32_t b0, uint32_t b1) {
    asm volatile(
        "mma.sync.aligned.m16n8k16.row.col.f32.f16.f16.f32 "
        "{%0,%1,%2,%3}, {%4,%5,%6,%7}, {%8,%9}, {%0,%1,%2,%3};"
        : "+f"(c[0]), "+f"(c[1]), "+f"(c[2]), "+f"(c[3])
        : "r"(a[0]), "r"(a[1]), "r"(a[2]), "r"(a[3]), "r"(b0), "r"(b1));
}
__device__ __forceinline__ void cp16(uint32_t dst_smem, const uint4* src) {
    asm volatile("cp.async.cg.shared.global [%0], [%1], 16;"
                 :: "r"(dst_smem), "l"(src));
}

// ---------------------------------------------------------------------------
// Weight pre-split: one float4 -> one uint2 of hi halves + one of lo halves.
// ---------------------------------------------------------------------------
__global__ __launch_bounds__(256)
void split_weights(const float4* __restrict__ W, uint2* __restrict__ WH,
                   uint2* __restrict__ WL) {
    size_t j = (size_t)blockIdx.x * 256 + threadIdx.x;   // float4 index
    float4 v = W[j];
    __half h0, l0, h1, l1, h2, l2, h3, l3;
    split_f16(v.x, h0, l0); split_f16(v.y, h1, l1);
    split_f16(v.z, h2, l2); split_f16(v.w, h3, l3);
    WH[j] = make_uint2(pack2(h0, h1), pack2(h2, h3));
    WL[j] = make_uint2(pack2(l0, l1), pack2(l2, l3));
}

// ---------------------------------------------------------------------------
__global__ void init_kernel(const float* __restrict__ E,
                            const float* __restrict__ eh,
                            const float* __restrict__ ec) {
    int i = blockIdx.x * blockDim.x + threadIdx.x;   // 0 .. B*H
    int k = i & (H - 1);
    __half hi, lo;
    split_f16(E[SOS_INDEX * H + k], hi, lo);
    g_xH[i] = hi; g_xL[i] = lo;
    split_f16(eh[i], hi, lo);
    g_hH[i] = hi; g_hL[i] = lo;
    g_c[i] = ec[i];
}

#define BKH 64      // halves of K per tile
#define ROWU 9      // uint4 per SMEM row (8 data + 1 skew)
#define ROWH (ROWU*8)

// ---------------------------------------------------------------------------
// Logits GEMM: C[64 x V] = h * Wout^T + bias. 2-stage cp.async pipeline,
// scalar-LDS consumer (R13 golden inner loop). BN=128 -> grid 250 fits ONE
// occupancy wave (2 CTA/SM x 148 SMs = 296 slots), removing the 2-wave
// quantization loss of the BN=64/grid-500 configuration.
// ---------------------------------------------------------------------------
template<int KTOT, int BN>
__global__ __launch_bounds__(256)
void logits_gemm(const uint4* __restrict__ BaH, const uint4* __restrict__ BaL,
                 const float* __restrict__ bias1, float* __restrict__ out, int ldc) {
    constexpr int NF  = BN / 16;
    constexpr int BR  = BN / 32;
    constexpr int STG = (128 + 2 * BN) * ROWU;
    constexpr int NT  = KTOT / BKH;
    extern __shared__ uint4 smem[];

    const int n0blk = blockIdx.x * BN;
    const int tid   = threadIdx.x;
    const int warp  = tid >> 5;
    const int lane  = tid & 31;
    const int gid   = lane >> 2;
    const int tig   = lane & 3;

    const int m0  = (warp >> 1) * 16;
    const int n0w = (warp & 1) * (BN / 2);

    const int lm  = tid >> 3;
    const int lv  = tid & 7;

    auto issue_tile = [&](int k0, int stage) {
        uint4* sb = smem + (size_t)stage * STG;
        const int kv = (k0 >> 3) + lv;
        #pragma unroll
        for (int r = 0; r < 2; r++) {
            int m = lm + r * 32;
            uint32_t dH = (uint32_t)__cvta_generic_to_shared(sb + m * ROWU + lv);
            uint32_t dL = (uint32_t)__cvta_generic_to_shared(sb + (64 + m) * ROWU + lv);
            cp16(dH, g_hH_raw + m * (H / 8) + kv);
            cp16(dL, g_hL_raw + m * (H / 8) + kv);
        }
        #pragma unroll
        for (int r = 0; r < BR; r++) {
            int nloc = lm + r * 32;
            size_t n = (size_t)n0blk + nloc;
            uint32_t dH = (uint32_t)__cvta_generic_to_shared(sb + (128 + nloc) * ROWU + lv);
            uint32_t dL = (uint32_t)__cvta_generic_to_shared(sb + (128 + BN + nloc) * ROWU + lv);
            cp16(dH, BaH + n * (KTOT / 8) + kv);
            cp16(dL, BaL + n * (KTOT / 8) + kv);
        }
        asm volatile("cp.async.commit_group;" ::: "memory");
    };

    float c1[NF][4], c2[NF][4];
    #pragma unroll
    for (int nf = 0; nf < NF; nf++)
        #pragma unroll
        for (int j = 0; j < 4; j++) { c1[nf][j] = 0.f; c2[nf][j] = 0.f; }

    issue_tile(0, 0);

    #pragma unroll 1
    for (int kt = 0; kt < NT; kt++) {
        if (kt + 1 < NT) {
            issue_tile((kt + 1) * BKH, (kt + 1) & 1);
            asm volatile("cp.async.wait_group 1;" ::: "memory");
        } else {
            asm volatile("cp.async.wait_group 0;" ::: "memory");
        }
        __syncthreads();

        const __half* base = (const __half*)(smem + (size_t)(kt & 1) * STG);
        const __half* AsH = base;
        const __half* AsL = base + 64 * ROWH;
        const __half* BsH = base + 128 * ROWH;
        const __half* BsL = base + (128 + BN) * ROWH;

        #pragma unroll
        for (int ks = 0; ks < BKH / 16; ks++) {
            const int kb = ks * 16;
            const int ra = (m0 + gid) * ROWH, rb = (m0 + gid + 8) * ROWH;
            uint32_t ah[4], al[4];
            ah[0] = *reinterpret_cast<const uint32_t*>(AsH + ra + kb + 2 * tig);
            ah[1] = *reinterpret_cast<const uint32_t*>(AsH + rb + kb + 2 * tig);
            ah[2] = *reinterpret_cast<const uint32_t*>(AsH + ra + kb + 8 + 2 * tig);
            ah[3] = *reinterpret_cast<const uint32_t*>(AsH + rb + kb + 8 + 2 * tig);
            al[0] = *reinterpret_cast<const uint32_t*>(AsL + ra + kb + 2 * tig);
            al[1] = *reinterpret_cast<const uint32_t*>(AsL + rb + kb + 2 * tig);
            al[2] = *reinterpret_cast<const uint32_t*>(AsL + ra + kb + 8 + 2 * tig);
            al[3] = *reinterpret_cast<const uint32_t*>(AsL + rb + kb + 8 + 2 * tig);

            uint32_t bh[NF][2];
            #pragma unroll
            for (int nf = 0; nf < NF; nf++) {
                int n = (n0w + nf * 8 + gid) * ROWH;
                bh[nf][0] = *reinterpret_cast<const uint32_t*>(BsH + n + kb + 2 * tig);
                bh[nf][1] = *reinterpret_cast<const uint32_t*>(BsH + n + kb + 8 + 2 * tig);
            }
            #pragma unroll
            for (int nf = 0; nf < NF; nf++) mma_f16(c2[nf], al, bh[nf][0], bh[nf][1]);
            #pragma unroll
            for (int nf = 0; nf < NF; nf++) mma_f16(c1[nf], ah, bh[nf][0], bh[nf][1]);
            #pragma unroll
            for (int nf = 0; nf < NF; nf++) {
                int n = (n0w + nf * 8 + gid) * ROWH;
                uint32_t bl0 = *reinterpret_cast<const uint32_t*>(BsL + n + kb + 2 * tig);
                uint32_t bl1 = *reinterpret_cast<const uint32_t*>(BsL + n + kb + 8 + 2 * tig);
                mma_f16(c2[nf], ah, bl0, bl1);
            }
        }
        __syncthreads();
    }

    const int mr0 = m0 + gid;
    const int mr1 = m0 + gid + 8;
    #pragma unroll
    for (int nf = 0; nf < NF; nf++) {
        int nn = n0blk + n0w + nf * 8 + tig * 2;
        float b0 = bias1[nn];
        float b1 = bias1[nn + 1];
        out[(size_t)mr0 * ldc + nn]     = c1[nf][0] + c2[nf][0] * RINV + b0;
        out[(size_t)mr0 * ldc + nn + 1] = c1[nf][1] + c2[nf][1] * RINV + b1;
        out[(size_t)mr1 * ldc + nn]     = c1[nf][2] + c2[nf][2] * RINV + b0;
        out[(size_t)mr1 * ldc + nn + 1] = c1[nf][3] + c2[nf][3] * RINV + b1;
    }
}

// ---------------------------------------------------------------------------
// FUSED gates GEMM + LSTM cell (unchanged from R15).
// ---------------------------------------------------------------------------
__global__ __launch_bounds__(256)
void gates_cell_gemm(const uint4* __restrict__ WihH, const uint4* __restrict__ WihL,
                     const uint4* __restrict__ WhhH, const uint4* __restrict__ WhhL,
                     const float* __restrict__ bih, const float* __restrict__ bhh) {
    constexpr int BN  = 32;
    constexpr int NF  = 2;
    constexpr int STG = (128 + 2 * BN) * ROWU;
    constexpr int KTOT = 2 * H;
    constexpr int NT  = KTOT / BKH;
    extern __shared__ uint4 smem[];

    const int J0  = blockIdx.x * 8;        // j-range of this block
    const int tid = threadIdx.x;
    const int warp = tid >> 5;
    const int lane = tid & 31;
    const int gid  = lane >> 2;
    const int tig  = lane & 3;

    const int m0  = (warp >> 1) * 16;
    const int n0w = (warp & 1) * (BN / 2);

    const int lm  = tid >> 3;
    const int lv  = tid & 7;

    auto grow_of = [&](int nloc) { return (nloc >> 3) * H + J0 + (nloc & 7); };

    auto issue_tile = [&](int k0, int stage) {
        uint4* sb = smem + (size_t)stage * STG;
        const int kv = (k0 >> 3) + lv;
        #pragma unroll
        for (int r = 0; r < 2; r++) {
            int m = lm + r * 32;
            uint32_t dH = (uint32_t)__cvta_generic_to_shared(sb + m * ROWU + lv);
            uint32_t dL = (uint32_t)__cvta_generic_to_shared(sb + (64 + m) * ROWU + lv);
            if (kv < H / 8) {
                cp16(dH, g_xH_raw + m * (H / 8) + kv);
                cp16(dL, g_xL_raw + m * (H / 8) + kv);
            } else {
                cp16(dH, g_hH_raw + m * (H / 8) + kv - H / 8);
                cp16(dL, g_hL_raw + m * (H / 8) + kv - H / 8);
            }
        }
        {
            int nloc = lm;                  // BR = 1 for BN=32
            size_t n = (size_t)grow_of(nloc);
            uint32_t dH = (uint32_t)__cvta_generic_to_shared(sb + (128 + nloc) * ROWU + lv);
            uint32_t dL = (uint32_t)__cvta_generic_to_shared(sb + (128 + BN + nloc) * ROWU + lv);
            if (kv < H / 8) {
                cp16(dH, WihH + n * (H / 8) + kv);
                cp16(dL, WihL + n * (H / 8) + kv);
            } else {
                cp16(dH, WhhH + n * (H / 8) + kv - H / 8);
                cp16(dL, WhhL + n * (H / 8) + kv - H / 8);
            }
        }
        asm volatile("cp.async.commit_group;" ::: "memory");
    };

    float c1[NF][4], c2[NF][4];
    #pragma unroll
    for (int nf = 0; nf < NF; nf++)
        #pragma unroll
        for (int j = 0; j < 4; j++) { c1[nf][j] = 0.f; c2[nf][j] = 0.f; }

    issue_tile(0, 0);

    #pragma unroll 1
    for (int kt = 0; kt < NT; kt++) {
        if (kt + 1 < NT) {
            issue_tile((kt + 1) * BKH, (kt + 1) & 1);
            asm volatile("cp.async.wait_group 1;" ::: "memory");
        } else {
            asm volatile("cp.async.wait_group 0;" ::: "memory");
        }
        __syncthreads();

        const __half* base = (const __half*)(smem + (size_t)(kt & 1) * STG);
        const __half* AsH = base;
        const __half* AsL = base + 64 * ROWH;
        const __half* BsH = base + 128 * ROWH;
        const __half* BsL = base + (128 + BN) * ROWH;

        #pragma unroll
        for (int ks = 0; ks < BKH / 16; ks++) {
            const int kb = ks * 16;
            const int ra = (m0 + gid) * ROWH, rb = (m0 + gid + 8) * ROWH;
            uint32_t ah[4], al[4];
            ah[0] = *reinterpret_cast<const uint32_t*>(AsH + ra + kb + 2 * tig);
            ah[1] = *reinterpret_cast<const uint32_t*>(AsH + rb + kb + 2 * tig);
            ah[2] = *reinterpret_cast<const uint32_t*>(AsH + ra + kb + 8 + 2 * tig);
            ah[3] = *reinterpret_cast<const uint32_t*>(AsH + rb + kb + 8 + 2 * tig);
            al[0] = *reinterpret_cast<const uint32_t*>(AsL + ra + kb + 2 * tig);
            al[1] = *reinterpret_cast<const uint32_t*>(AsL + rb + kb + 2 * tig);
            al[2] = *reinterpret_cast<const uint32_t*>(AsL + ra + kb + 8 + 2 * tig);
            al[3] = *reinterpret_cast<const uint32_t*>(AsL + rb + kb + 8 + 2 * tig);

            uint32_t bh[NF][2];
            #pragma unroll
            for (int nf = 0; nf < NF; nf++) {
                int n = (n0w + nf * 8 + gid) * ROWH;
                bh[nf][0] = *reinterpret_cast<const uint32_t*>(BsH + n + kb + 2 * tig);
                bh[nf][1] = *reinterpret_cast<const uint32_t*>(BsH + n + kb + 8 + 2 * tig);
            }
            #pragma unroll
            for (int nf = 0; nf < NF; nf++) mma_f16(c2[nf], al, bh[nf][0], bh[nf][1]);
            #pragma unroll
            for (int nf = 0; nf < NF; nf++) mma_f16(c1[nf], ah, bh[nf][0], bh[nf][1]);
            #pragma unroll
            for (int nf = 0; nf < NF; nf++) {
                int n = (n0w + nf * 8 + gid) * ROWH;
                uint32_t bl0 = *reinterpret_cast<const uint32_t*>(BsL + n + kb + 2 * tig);
                uint32_t bl1 = *reinterpret_cast<const uint32_t*>(BsL + n + kb + 8 + 2 * tig);
                mma_f16(c2[nf], ah, bl0, bl1);
            }
        }
        __syncthreads();
    }

    // ---- epilogue: spill gate tile (64 x 32) to SMEM, then fused cell ----
    float* sg = (float*)smem;
    const int mr0 = m0 + gid;
    const int mr1 = m0 + gid + 8;
    #pragma unroll
    for (int nf = 0; nf < NF; nf++) {
        int nloc = n0w + nf * 8 + tig * 2;
        int gr0 = grow_of(nloc), gr1 = grow_of(nloc + 1);
        float b0 = bih[gr0] + bhh[gr0];
        float b1 = bih[gr1] + bhh[gr1];
        sg[mr0 * 32 + nloc]     = c1[nf][0] + c2[nf][0] * RINV + b0;
        sg[mr0 * 32 + nloc + 1] = c1[nf][1] + c2[nf][1] * RINV + b1;
        sg[mr1 * 32 + nloc]     = c1[nf][2] + c2[nf][2] * RINV + b0;
        sg[mr1 * 32 + nloc + 1] = c1[nf][3] + c2[nf][3] * RINV + b1;
    }
    __syncthreads();

    #pragma unroll
    for (int e = tid; e < 512; e += 256) {
        int b = e >> 3, r = e & 7;
        float ig = sg[b * 32 + r];
        float fg = sg[b * 32 + 8 + r];
        float gg = sg[b * 32 + 16 + r];
        float og = sg[b * 32 + 24 + r];
        int idx = b * H + J0 + r;
        float c  = g_c[idx];
        float si = 1.f / (1.f + expf(-ig));
        float sf = 1.f / (1.f + expf(-fg));
        float so = 1.f / (1.f + expf(-og));
        float cn = sf * c + si * tanhf(gg);
        float hn = so * tanhf(cn);
        g_c[idx] = cn;
        __half hi, lo;
        split_f16(hn, hi, lo);
        g_hH[idx] = hi; g_hL[idx] = lo;
    }
}

// ---------------------------------------------------------------------------
// Per-batch-row: argmax (first-index tiebreak), softmax EOS prob,
// greedy feedback gather x_next = E[argmax] written pre-split (scalar).
// ---------------------------------------------------------------------------
__global__ __launch_bounds__(1024)
void softmax_argmax(const float* __restrict__ logits, const float* __restrict__ E,
                    float* __restrict__ mask_out) {
    const int b    = blockIdx.x;
    const int tid  = threadIdx.x;
    const int lane = tid & 31;
    const int wrp  = tid >> 5;
    const float4* row4 = reinterpret_cast<const float4*>(logits + (size_t)b * V);

    float best = -INFINITY; int besti = 0x7fffffff;
    for (int q = tid; q < V / 4; q += 1024) {
        float4 x = row4[q];
        int v = q * 4;
        if (x.x > best) { best = x.x; besti = v; }
        if (x.y > best) { best = x.y; besti = v + 1; }
        if (x.z > best) { best = x.z; besti = v + 2; }
        if (x.w > best) { best = x.w; besti = v + 3; }
    }
    #pragma unroll
    for (int s = 16; s > 0; s >>= 1) {
        float ov = __shfl_down_sync(0xffffffffu, best, s);
        int   oi = __shfl_down_sync(0xffffffffu, besti, s);
        if (ov > best || (ov == best && oi < besti)) { best = ov; besti = oi; }
    }
    __shared__ float swv[32];
    __shared__ int   swi[32];
    if (lane == 0) { swv[wrp] = best; swi[wrp] = besti; }
    __syncthreads();
    __shared__ float s_gmax;
    __shared__ int   s_amax;
    if (wrp == 0) {
        float bv = swv[lane]; int bi = swi[lane];
        #pragma unroll
        for (int s = 16; s > 0; s >>= 1) {
            float ov = __shfl_down_sync(0xffffffffu, bv, s);
            int   oi = __shfl_down_sync(0xffffffffu, bi, s);
            if (ov > bv || (ov == bv && oi < bi)) { bv = ov; bi = oi; }
        }
        if (lane == 0) { s_gmax = bv; s_amax = bi; }
    }
    __syncthreads();
    const float gmax = s_gmax;
    const int   amax = s_amax;

    float sum = 0.f;
    for (int q = tid; q < V / 4; q += 1024) {
        float4 x = row4[q];
        sum += expf(x.x - gmax) + expf(x.y - gmax)
             + expf(x.z - gmax) + expf(x.w - gmax);
    }
    #pragma unroll
    for (int s = 16; s > 0; s >>= 1)
        sum += __shfl_down_sync(0xffffffffu, sum, s);
    __shared__ float ssum[32];
    if (lane == 0) ssum[wrp] = sum;
    __syncthreads();
    if (wrp == 0) {
        float t = ssum[lane];
        #pragma unroll
        for (int s = 16; s > 0; s >>= 1)
            t += __shfl_down_sync(0xffffffffu, t, s);
        if (lane == 0)
            mask_out[b] = expf(logits[(size_t)b * V + EOS_INDEX] - gmax) / t;
    }

    // greedy feedback: x_next = E[argmax], stored pre-split (scalar 2B)
    __half hi, lo;
    split_f16(E[(size_t)amax * H + tid], hi, lo);
    g_xH[b * H + tid] = hi;
    g_xL[b * H + tid] = lo;
}

// ---------------------------------------------------------------------------
extern "C" void kernel_launch(void* const* d_in, const int* in_sizes, int n_in,
                              void* d_out, int out_size) {
    const float* E    = (const float*)d_in[0];
    const float* Wih  = (const float*)d_in[1];
    const float* Whh  = (const float*)d_in[2];
    const float* bih  = (const float*)d_in[3];
    const float* bhh  = (const float*)d_in[4];
    const float* Wout = (const float*)d_in[5];
    const float* bout = (const float*)d_in[6];
    const float* eh   = (const float*)d_in[7];
    const float* ec   = (const float*)d_in[8];

    float* out   = (float*)d_out;                       // [T][B][V] logits
    float* masks = out + (size_t)T * B * V;             // [T][B]

    // Resolve DEVICE addresses of all symbols passed as kernel args.
    void *pWihH, *pWihL, *pWhhH, *pWhhL, *pWoutH, *pWoutL;
    cudaGetSymbolAddress(&pWihH, g_WihH_raw);
    cudaGetSymbolAddress(&pWihL, g_WihL_raw);
    cudaGetSymbolAddress(&pWhhH, g_WhhH_raw);
    cudaGetSymbolAddress(&pWhhL, g_WhhL_raw);
    cudaGetSymbolAddress(&pWoutH, g_WoutH_raw);
    cudaGetSymbolAddress(&pWoutL, g_WoutL_raw);

    // Dynamic SMEM sizes (2 stages).
    const int smem_gates  = (128 + 2 * 32) * ROWU * 16 * 2;    // 55296 B
    const int smem_logits = (128 + 2 * 128) * ROWU * 16 * 2;   // 110592 B
    cudaFuncSetAttribute(gates_cell_gemm,
                         cudaFuncAttributeMaxDynamicSharedMemorySize, smem_gates);
    cudaFuncSetAttribute(logits_gemm<H, 128>,
                         cudaFuncAttributeMaxDynamicSharedMemorySize, smem_logits);

    // One-time (per launch) weight pre-split. grid = elems/4/256.
    split_weights<<<GATES * H / 1024, 256>>>(
        (const float4*)Wih, (uint2*)pWihH, (uint2*)pWihL);
    split_weights<<<GATES * H / 1024, 256>>>(
        (const float4*)Whh, (uint2*)pWhhH, (uint2*)pWhhL);
    split_weights<<<(int)((size_t)V * H / 1024), 256>>>(
        (const float4*)Wout, (uint2*)pWoutH, (uint2*)pWoutL);

    init_kernel<<<(B * H) / 256, 256>>>(E, eh, ec);
    for (int t = 0; t < T; t++) {
        float* lg = out + (size_t)t * B * V;
        // fused gates GEMM + cell: 128 blocks (8 j-values each)
        gates_cell_gemm<<<H / 8, 256, smem_gates>>>(
            (const uint4*)pWihH, (const uint4*)pWihL,
            (const uint4*)pWhhH, (const uint4*)pWhhL, bih, bhh);
        // logits: [64 x 32000] = h * Wout^T, BN=128 -> 250 blocks (1 wave)
        logits_gemm<H, 128><<<V / 128, 256, smem_logits>>>(
            (const uint4*)pWoutH, (const uint4*)pWoutL, bout, lg, V);
        softmax_argmax<<<B, 1024>>>(lg, E, masks + t * B);
    }
}